// round 7
// baseline (speedup 1.0000x reference)
#include <cuda_runtime.h>
#include <cuda_bf16.h>
#include <cstdint>

// GAT layer (sm_100 baseline ISA):
//  Fork/join graph (6 nodes):
//   stream0: K1 GEMM (bf16x3 HMMA) + scores -----------------\
//   streamB: K2 hist -> K3 lookback scan -> K4 scatter        } -> K5 aggregate
//  g_cnt is self-clearing (scan zeroes after read); hist zeroes scan status.
// Adjacency arrives as int32 (JAX x64 off).

#define D_IN  128
#define D_OUT 64
#define N_NODES_MAX 100000
#define N_EDGES_MAX 1000000
#define NSCAN_PAD   100352
#define SHIFT_C 8.0f

#define FLAG_AGG 0x40000000u
#define FLAG_INC 0x80000000u
#define VAL_MASK 0x3FFFFFFFu

// ---- scratch (__device__ globals; allocation-free rule) ----
__device__ float g_wx   [N_NODES_MAX * D_OUT];
__device__ float g_ssrc [N_NODES_MAX];
__device__ float g_strg [N_NODES_MAX];
__device__ int   g_cnt  [NSCAN_PAD];         // zero at load; self-clearing
__device__ int   g_rowst[NSCAN_PAD];
__device__ int   g_curs [NSCAN_PAD];
__device__ unsigned g_stat[128];             // lookback status; hist re-zeroes
__device__ int   g_perm [N_EDGES_MAX];
__device__ float g_ex   [N_EDGES_MAX];

// ---- helpers ----
__device__ __forceinline__ void mma_bf16(float* c, uint32_t a0, uint32_t a1,
                                         uint32_t a2, uint32_t a3,
                                         uint32_t b0, uint32_t b1) {
    asm volatile(
        "mma.sync.aligned.m16n8k16.row.col.f32.bf16.bf16.f32 "
        "{%0,%1,%2,%3}, {%4,%5,%6,%7}, {%8,%9}, {%0,%1,%2,%3};"
        : "+f"(c[0]), "+f"(c[1]), "+f"(c[2]), "+f"(c[3])
        : "r"(a0), "r"(a1), "r"(a2), "r"(a3), "r"(b0), "r"(b1));
}
__device__ __forceinline__ uint16_t f2bf_bits(float x) {
    uint16_t u; asm("cvt.rn.bf16.f32 %0, %1;" : "=h"(u) : "f"(x)); return u;
}
__device__ __forceinline__ float bf_bits2f(uint16_t u) {
    return __uint_as_float((uint32_t)u << 16);
}

#define A_STRIDE 272
#define OFF_ALO  34816
#define OFF_BHI  69632
#define OFF_BLO  87040
#define GEMM_SMEM_BYTES 104448

// ---------------------------------------------------------------------------
// K1: bf16x3 HMMA GEMM. CTA = 128 rows x 64 cols x K=128, 8 warps.
// ---------------------------------------------------------------------------
__global__ __launch_bounds__(256, 2) void k_gemm_mma(
    const float* __restrict__ X, const float* __restrict__ W,
    const float* __restrict__ a, int n_nodes)
{
    extern __shared__ char smem[];
    const int tid   = threadIdx.x;
    const int warp  = tid >> 5;
    const int lane  = tid & 31;
    const int r     = lane >> 2;
    const int c     = lane & 3;
    const int node0 = blockIdx.x * 128;

    // ---- load X tile -> Ahi/Alo (paired bf16 converts) ----
    {
        const float4* X4 = reinterpret_cast<const float4*>(X);
        #pragma unroll
        for (int it = 0; it < 16; it++) {
            int idx = tid + it * 256;
            int row = idx >> 5;
            int kq  = idx & 31;
            float4 v = make_float4(0.f, 0.f, 0.f, 0.f);
            if (node0 + row < n_nodes) v = X4[(size_t)(node0 + row) * 32 + kq];

            __nv_bfloat162 h01 = __floats2bfloat162_rn(v.x, v.y);
            __nv_bfloat162 h23 = __floats2bfloat162_rn(v.z, v.w);
            float l0 = v.x - __low2float(h01);
            float l1 = v.y - __high2float(h01);
            float l2 = v.z - __low2float(h23);
            float l3 = v.w - __high2float(h23);
            __nv_bfloat162 l01 = __floats2bfloat162_rn(l0, l1);
            __nv_bfloat162 l23 = __floats2bfloat162_rn(l2, l3);

            char* p = smem + row * A_STRIDE + kq * 8;
            *reinterpret_cast<uint2*>(p) =
                make_uint2(*reinterpret_cast<uint32_t*>(&h01),
                           *reinterpret_cast<uint32_t*>(&h23));
            *reinterpret_cast<uint2*>(p + OFF_ALO) =
                make_uint2(*reinterpret_cast<uint32_t*>(&l01),
                           *reinterpret_cast<uint32_t*>(&l23));
        }
    }
    // ---- load W -> Bhi/Blo transposed ([n][k], stride 272B) ----
    {
        #pragma unroll
        for (int it = 0; it < 32; it++) {
            int idx = tid + it * 256;
            int k = idx >> 6, n = idx & 63;
            float w = W[idx];
            uint16_t h = f2bf_bits(w);
            uint16_t l = f2bf_bits(w - bf_bits2f(h));
            char* p = smem + OFF_BHI + n * A_STRIDE + k * 2;
            *reinterpret_cast<uint16_t*>(p) = h;
            *reinterpret_cast<uint16_t*>(p + (OFF_BLO - OFF_BHI)) = l;
        }
    }
    __syncthreads();

    float acc[8][4];
    #pragma unroll
    for (int nt = 0; nt < 8; nt++)
        #pragma unroll
        for (int j = 0; j < 4; j++) acc[nt][j] = 0.0f;

    const char* pA0 = smem + (warp * 16 + r) * A_STRIDE + c * 4;
    #pragma unroll
    for (int kk = 0; kk < 8; kk++) {
        const int k0b = kk * 32;
        uint32_t ah0 = *reinterpret_cast<const uint32_t*>(pA0 + k0b);
        uint32_t ah1 = *reinterpret_cast<const uint32_t*>(pA0 + 8 * A_STRIDE + k0b);
        uint32_t ah2 = *reinterpret_cast<const uint32_t*>(pA0 + k0b + 16);
        uint32_t ah3 = *reinterpret_cast<const uint32_t*>(pA0 + 8 * A_STRIDE + k0b + 16);
        uint32_t al0 = *reinterpret_cast<const uint32_t*>(pA0 + OFF_ALO + k0b);
        uint32_t al1 = *reinterpret_cast<const uint32_t*>(pA0 + OFF_ALO + 8 * A_STRIDE + k0b);
        uint32_t al2 = *reinterpret_cast<const uint32_t*>(pA0 + OFF_ALO + k0b + 16);
        uint32_t al3 = *reinterpret_cast<const uint32_t*>(pA0 + OFF_ALO + 8 * A_STRIDE + k0b + 16);
        #pragma unroll
        for (int nt = 0; nt < 8; nt++) {
            const char* pB = smem + OFF_BHI + (nt * 8 + r) * A_STRIDE + c * 4 + k0b;
            uint32_t bh0 = *reinterpret_cast<const uint32_t*>(pB);
            uint32_t bh1 = *reinterpret_cast<const uint32_t*>(pB + 16);
            uint32_t bl0 = *reinterpret_cast<const uint32_t*>(pB + (OFF_BLO - OFF_BHI));
            uint32_t bl1 = *reinterpret_cast<const uint32_t*>(pB + (OFF_BLO - OFF_BHI) + 16);
            mma_bf16(acc[nt], ah0, ah1, ah2, ah3, bh0, bh1);
            mma_bf16(acc[nt], ah0, ah1, ah2, ah3, bl0, bl1);
            mma_bf16(acc[nt], al0, al1, al2, al3, bh0, bh1);
        }
    }

    // ---- score epilogue ----
    {
        float ps0 = 0.f, pt0 = 0.f, ps1 = 0.f, pt1 = 0.f;
        #pragma unroll
        for (int nt = 0; nt < 8; nt++) {
            #pragma unroll
            for (int j = 0; j < 2; j++) {
                int col = nt * 8 + 2 * c + j;
                float av = __ldg(&a[col]);
                float bv = __ldg(&a[64 + col]);
                ps0 = fmaf(acc[nt][j],     av, ps0);
                pt0 = fmaf(acc[nt][j],     bv, pt0);
                ps1 = fmaf(acc[nt][2 + j], av, ps1);
                pt1 = fmaf(acc[nt][2 + j], bv, pt1);
            }
        }
        #pragma unroll
        for (int o = 1; o <= 2; o <<= 1) {
            ps0 += __shfl_xor_sync(0xffffffffu, ps0, o);
            pt0 += __shfl_xor_sync(0xffffffffu, pt0, o);
            ps1 += __shfl_xor_sync(0xffffffffu, ps1, o);
            pt1 += __shfl_xor_sync(0xffffffffu, pt1, o);
        }
        if (c == 0) {
            int n0 = node0 + warp * 16 + r;
            int n1 = n0 + 8;
            if (n0 < n_nodes) { g_ssrc[n0] = ps0; g_strg[n0] = pt0; }
            if (n1 < n_nodes) { g_ssrc[n1] = ps1; g_strg[n1] = pt1; }
        }
    }

    __syncthreads();

    // ---- restage acc -> S[row][col] (pad 68) for coalesced STG ----
    float* S = reinterpret_cast<float*>(smem);
    {
        const int row0 = warp * 16 + r;
        #pragma unroll
        for (int nt = 0; nt < 8; nt++) {
            *reinterpret_cast<float2*>(&S[row0 * 68 + nt * 8 + 2 * c]) =
                make_float2(acc[nt][0], acc[nt][1]);
            *reinterpret_cast<float2*>(&S[(row0 + 8) * 68 + nt * 8 + 2 * c]) =
                make_float2(acc[nt][2], acc[nt][3]);
        }
    }
    __syncthreads();
    {
        float4* wx4 = reinterpret_cast<float4*>(g_wx);
        #pragma unroll
        for (int it = 0; it < 8; it++) {
            int idx = tid + it * 256;
            int row = idx >> 4, cq = idx & 15;
            if (node0 + row < n_nodes)
                wx4[(size_t)(node0 + row) * 16 + cq] =
                    *reinterpret_cast<const float4*>(&S[row * 68 + cq * 4]);
        }
    }
}

// ---------------------------------------------------------------------------
// K2: histogram of src (int4 loads); block 0 zeroes the scan status array.
// ---------------------------------------------------------------------------
__global__ void k_hist(const int* __restrict__ src, int n_edges) {
    if (blockIdx.x == 0 && threadIdx.x < 128) g_stat[threadIdx.x] = 0u;
    int e4 = (blockIdx.x * blockDim.x + threadIdx.x) * 4;
    if (e4 + 3 < n_edges) {
        int4 s = *reinterpret_cast<const int4*>(src + e4);
        atomicAdd(&g_cnt[s.x], 1);
        atomicAdd(&g_cnt[s.y], 1);
        atomicAdd(&g_cnt[s.z], 1);
        atomicAdd(&g_cnt[s.w], 1);
    } else {
        for (int e = e4; e < n_edges; e++) atomicAdd(&g_cnt[src[e]], 1);
    }
}

// ---------------------------------------------------------------------------
// K3: single-kernel decoupled-lookback exclusive scan of g_cnt -> g_rowst/g_curs.
// Also zeroes g_cnt after reading (self-clearing for graph replay).
// 98 blocks x 1024 threads, all resident on 148 SMs -> spin-safe.
// Status word: value (<=1e6) | FLAG_AGG / FLAG_INC, single-word protocol.
// ---------------------------------------------------------------------------
__device__ __forceinline__ int warp_incl_scan(int v, int lane) {
    #pragma unroll
    for (int o = 1; o < 32; o <<= 1) {
        int t = __shfl_up_sync(0xffffffffu, v, o);
        if (lane >= o) v += t;
    }
    return v;
}

__global__ __launch_bounds__(1024) void k_scan_lb(int n, int n_nodes) {
    __shared__ int ws[32];
    __shared__ int s_prev;
    const int tid  = threadIdx.x;
    const int lane = tid & 31;
    const int wid  = tid >> 5;
    const int b    = blockIdx.x;
    const int i    = b * 1024 + tid;

    int v = (i < n) ? g_cnt[i] : 0;
    if (i < n) g_cnt[i] = 0;                 // self-clear for next replay

    int s = warp_incl_scan(v, lane);
    if (lane == 31) ws[wid] = s;
    __syncthreads();
    if (wid == 0) {
        int bsum = ws[lane];
        int sb = warp_incl_scan(bsum, lane);
        ws[lane] = sb - bsum;                // exclusive warp offsets
    }
    __syncthreads();
    const int incl  = s + ws[wid];           // inclusive within block
    const int total = __shfl_sync(0xffffffffu, incl, 31, 32);  // only valid in last warp

    // publish: b==0 -> INC immediately; else AGG (single-word store)
    if (tid == 1023) {
        unsigned pk = (unsigned)incl;        // == block total
        g_stat[b] = pk | (b == 0 ? FLAG_INC : FLAG_AGG);
    }
    __syncthreads();

    // lookback (thread 0)
    if (tid == 0) {
        int prev = 0;
        if (b > 0) {
            int j = b - 1;
            while (true) {
                unsigned st = *(volatile unsigned*)&g_stat[j];
                if (st == 0u) continue;
                prev += (int)(st & VAL_MASK);
                if (st & FLAG_INC) break;
                j--;
            }
        }
        s_prev = prev;
    }
    __syncthreads();
    const int prev = s_prev;

    // publish inclusive prefix for later blocks
    if (tid == 1023 && b > 0)
        *(volatile unsigned*)&g_stat[b] = ((unsigned)(incl + prev)) | FLAG_INC;

    if (i < n) {
        int excl = prev + incl - v;
        g_rowst[i] = excl;
        if (i < n_nodes) g_curs[i] = excl;
    }
}

// ---------------------------------------------------------------------------
// K4: counting-sort scatter (stores trg node ids)
// ---------------------------------------------------------------------------
__global__ void k_scatter(const int* __restrict__ src, const int* __restrict__ trg,
                          int n_edges) {
    int e = blockIdx.x * blockDim.x + threadIdx.x;
    if (e >= n_edges) return;
    int s = src[e];
    int p = atomicAdd(&g_curs[s], 1);
    g_perm[p] = trg[e];
}

// ---------------------------------------------------------------------------
// K5: one warp per node; constant-shift exp (cancels exactly in ratio).
// ---------------------------------------------------------------------------
__global__ __launch_bounds__(256) void k_aggregate(float* __restrict__ out,
                                                   int n_nodes) {
    const int warp = (blockIdx.x * blockDim.x + threadIdx.x) >> 5;
    const int lane = threadIdx.x & 31;
    if (warp >= n_nodes) return;

    const int beg = g_rowst[warp];
    const int end = g_rowst[warp + 1];
    const int deg = end - beg;
    const float ss = g_ssrc[warp];

    float den = 0.0f;
    float ex_l = 0.0f;
    int   t_l  = 0;

    if (deg <= 32) {
        if (lane < deg) {
            t_l = g_perm[beg + lane];
            float l = ss + g_strg[t_l];
            l = (l >= 0.0f) ? l : 0.2f * l;
            ex_l = __expf(l - SHIFT_C);
            den = ex_l;
        }
    } else {
        for (int i = beg + lane; i < end; i += 32) {
            int t = g_perm[i];
            float l = ss + g_strg[t];
            l = (l >= 0.0f) ? l : 0.2f * l;
            float ex = __expf(l - SHIFT_C);
            g_ex[i] = ex;
            den += ex;
        }
        __syncwarp();
    }
    #pragma unroll
    for (int o = 16; o > 0; o >>= 1)
        den += __shfl_xor_sync(0xffffffffu, den, o);
    const float inv = (den > 0.0f) ? (1.0f / den) : 0.0f;

    float2 acc = make_float2(0.0f, 0.0f);
    if (deg <= 32) {
        for (int j = 0; j < deg; j++) {
            float alpha = __shfl_sync(0xffffffffu, ex_l, j) * inv;
            int   t     = __shfl_sync(0xffffffffu, t_l, j);
            float2 v = *reinterpret_cast<const float2*>(&g_wx[(size_t)t * D_OUT + lane * 2]);
            acc.x = fmaf(alpha, v.x, acc.x);
            acc.y = fmaf(alpha, v.y, acc.y);
        }
    } else {
        for (int i = beg; i < end; i++) {
            float alpha = g_ex[i] * inv;
            int   t     = g_perm[i];
            float2 v = *reinterpret_cast<const float2*>(&g_wx[(size_t)t * D_OUT + lane * 2]);
            acc.x = fmaf(alpha, v.x, acc.x);
            acc.y = fmaf(alpha, v.y, acc.y);
        }
    }
    *reinterpret_cast<float2*>(&out[(size_t)warp * D_OUT + lane * 2]) = acc;
}

// ---------------------------------------------------------------------------
extern "C" void kernel_launch(void* const* d_in, const int* in_sizes, int n_in,
                              void* d_out, int out_size)
{
    const float* X   = (const float*)d_in[0];
    const float* W   = (const float*)d_in[1];
    const float* a   = (const float*)d_in[2];
    const int*   adj = (const int*)d_in[3];

    const int n_nodes = in_sizes[0] / D_IN;
    const int n_edges = in_sizes[3] / 2;
    const int* src = adj;
    const int* trg = adj + n_edges;
    float* out = (float*)d_out;

    const int nscan = n_nodes + 1;

    static cudaStream_t sB = nullptr;
    static cudaEvent_t  evFork = nullptr, evJoin = nullptr;
    if (sB == nullptr) {
        cudaFuncSetAttribute(k_gemm_mma, cudaFuncAttributeMaxDynamicSharedMemorySize,
                             GEMM_SMEM_BYTES);
        cudaStreamCreateWithFlags(&sB, cudaStreamNonBlocking);
        cudaEventCreateWithFlags(&evFork, cudaEventDisableTiming);
        cudaEventCreateWithFlags(&evJoin, cudaEventDisableTiming);
    }

    // ---- fork ----
    cudaEventRecord(evFork, 0);
    cudaStreamWaitEvent(sB, evFork, 0);

    // chain B (adjacency only): hist -> lookback scan -> scatter
    {
        int e4 = (n_edges + 3) / 4;
        k_hist<<<(e4 + 255) / 256, 256, 0, sB>>>(src, n_edges);
    }
    k_scan_lb<<<(nscan + 1023) / 1024, 1024, 0, sB>>>(nscan, n_nodes);
    k_scatter<<<(n_edges + 255) / 256, 256, 0, sB>>>(src, trg, n_edges);
    cudaEventRecord(evJoin, sB);

    // chain A (X, W, a only)
    k_gemm_mma<<<(n_nodes + 127) / 128, 256, GEMM_SMEM_BYTES>>>(X, W, a, n_nodes);

    // ---- join ----
    cudaStreamWaitEvent(0, evJoin, 0);
    {
        long long threads = (long long)n_nodes * 32;
        k_aggregate<<<(int)((threads + 255) / 256), 256>>>(out, n_nodes);
    }
}

// round 8
// speedup vs baseline: 1.0296x; 1.0296x over previous
#include <cuda_runtime.h>
#include <cuda_bf16.h>
#include <cuda_fp16.h>
#include <cstdint>

// GAT layer (sm_100 baseline ISA):
//  Fork/join graph (6 nodes):
//   stream0: K1 GEMM (bf16x3 HMMA, K-split, 3 CTAs/SM) + scores --\
//   streamB: K2 hist -> K3 lookback scan -> K4 scatter             } -> K5
//  wx stored fp16 (half2) -> halves K5 gather + GEMM write traffic.
// Adjacency arrives as int32 (JAX x64 off).

#define D_IN  128
#define D_OUT 64
#define N_NODES_MAX 100000
#define N_EDGES_MAX 1000000
#define NSCAN_PAD   100352
#define SHIFT_C 8.0f

#define FLAG_AGG 0x40000000u
#define FLAG_INC 0x80000000u
#define VAL_MASK 0x3FFFFFFFu

// ---- scratch (__device__ globals; allocation-free rule) ----
__device__ unsigned g_wx16 [N_NODES_MAX * 32];   // half2 pairs, 12.8 MB
__device__ float g_ssrc [N_NODES_MAX];
__device__ float g_strg [N_NODES_MAX];
__device__ int   g_cnt  [NSCAN_PAD];             // zero at load; self-clearing
__device__ int   g_rowst[NSCAN_PAD];
__device__ int   g_curs [NSCAN_PAD];
__device__ unsigned g_stat[128];                 // lookback status; hist zeroes
__device__ int   g_perm [N_EDGES_MAX];
__device__ float g_ex   [N_EDGES_MAX];

// ---- helpers ----
__device__ __forceinline__ void mma_bf16(float* c, uint32_t a0, uint32_t a1,
                                         uint32_t a2, uint32_t a3,
                                         uint32_t b0, uint32_t b1) {
    asm volatile(
        "mma.sync.aligned.m16n8k16.row.col.f32.bf16.bf16.f32 "
        "{%0,%1,%2,%3}, {%4,%5,%6,%7}, {%8,%9}, {%0,%1,%2,%3};"
        : "+f"(c[0]), "+f"(c[1]), "+f"(c[2]), "+f"(c[3])
        : "r"(a0), "r"(a1), "r"(a2), "r"(a3), "r"(b0), "r"(b1));
}
__device__ __forceinline__ uint16_t f2bf_bits(float x) {
    uint16_t u; asm("cvt.rn.bf16.f32 %0, %1;" : "=h"(u) : "f"(x)); return u;
}
__device__ __forceinline__ float bf_bits2f(uint16_t u) {
    return __uint_as_float((uint32_t)u << 16);
}

// SMEM (per K-chunk of 64): stride 144B (64 bf16 + 8 pad) -> bank-safe (36w%32=4)
#define CH_STRIDE 144
#define OFF_ALO   18432
#define OFF_BHI   36864
#define OFF_BLO   46080
#define GEMM_SMEM_BYTES 55296

// ---------------------------------------------------------------------------
// K1: bf16x3 HMMA GEMM, K-split into 2 chunks of 64. CTA = 128 rows x 64 cols.
// 8 warps; warp owns 16 rows x all 64 cols.
// ---------------------------------------------------------------------------
__global__ __launch_bounds__(256, 3) void k_gemm_mma(
    const float* __restrict__ X, const float* __restrict__ W,
    const float* __restrict__ a, int n_nodes)
{
    extern __shared__ char smem[];
    const int tid   = threadIdx.x;
    const int warp  = tid >> 5;
    const int lane  = tid & 31;
    const int r     = lane >> 2;
    const int c     = lane & 3;
    const int node0 = blockIdx.x * 128;

    float acc[8][4];
    #pragma unroll
    for (int nt = 0; nt < 8; nt++)
        #pragma unroll
        for (int j = 0; j < 4; j++) acc[nt][j] = 0.0f;

    #pragma unroll
    for (int p = 0; p < 2; p++) {
        // ---- load X chunk -> Ahi/Alo ----
        {
            const float4* X4 = reinterpret_cast<const float4*>(X);
            #pragma unroll
            for (int it = 0; it < 8; it++) {
                int idx = tid + it * 256;        // 2048 float4
                int row = idx >> 4;              // 0..127
                int kq  = idx & 15;              // float4 within chunk
                float4 v = make_float4(0.f, 0.f, 0.f, 0.f);
                if (node0 + row < n_nodes)
                    v = X4[(size_t)(node0 + row) * 32 + p * 16 + kq];
                __nv_bfloat162 h01 = __floats2bfloat162_rn(v.x, v.y);
                __nv_bfloat162 h23 = __floats2bfloat162_rn(v.z, v.w);
                float l0 = v.x - __low2float(h01);
                float l1 = v.y - __high2float(h01);
                float l2 = v.z - __low2float(h23);
                float l3 = v.w - __high2float(h23);
                __nv_bfloat162 l01 = __floats2bfloat162_rn(l0, l1);
                __nv_bfloat162 l23 = __floats2bfloat162_rn(l2, l3);
                char* pp = smem + row * CH_STRIDE + kq * 8;
                *reinterpret_cast<uint2*>(pp) =
                    make_uint2(*reinterpret_cast<uint32_t*>(&h01),
                               *reinterpret_cast<uint32_t*>(&h23));
                *reinterpret_cast<uint2*>(pp + OFF_ALO) =
                    make_uint2(*reinterpret_cast<uint32_t*>(&l01),
                               *reinterpret_cast<uint32_t*>(&l23));
            }
        }
        // ---- load W chunk -> Bhi/Blo transposed ([n][k]) ----
        {
            #pragma unroll
            for (int it = 0; it < 16; it++) {
                int idx = tid + it * 256;        // 4096 scalars
                int k = idx >> 6, n = idx & 63;
                float w = W[(p * 64 + k) * 64 + n];
                uint16_t h = f2bf_bits(w);
                uint16_t l = f2bf_bits(w - bf_bits2f(h));
                char* pp = smem + OFF_BHI + n * CH_STRIDE + k * 2;
                *reinterpret_cast<uint16_t*>(pp) = h;
                *reinterpret_cast<uint16_t*>(pp + (OFF_BLO - OFF_BHI)) = l;
            }
        }
        __syncthreads();

        const char* pA0 = smem + (warp * 16 + r) * CH_STRIDE + c * 4;
        #pragma unroll
        for (int kk = 0; kk < 4; kk++) {
            const int k0b = kk * 32;
            uint32_t ah0 = *reinterpret_cast<const uint32_t*>(pA0 + k0b);
            uint32_t ah1 = *reinterpret_cast<const uint32_t*>(pA0 + 8 * CH_STRIDE + k0b);
            uint32_t ah2 = *reinterpret_cast<const uint32_t*>(pA0 + k0b + 16);
            uint32_t ah3 = *reinterpret_cast<const uint32_t*>(pA0 + 8 * CH_STRIDE + k0b + 16);
            uint32_t al0 = *reinterpret_cast<const uint32_t*>(pA0 + OFF_ALO + k0b);
            uint32_t al1 = *reinterpret_cast<const uint32_t*>(pA0 + OFF_ALO + 8 * CH_STRIDE + k0b);
            uint32_t al2 = *reinterpret_cast<const uint32_t*>(pA0 + OFF_ALO + k0b + 16);
            uint32_t al3 = *reinterpret_cast<const uint32_t*>(pA0 + OFF_ALO + 8 * CH_STRIDE + k0b + 16);
            #pragma unroll
            for (int nt = 0; nt < 8; nt++) {
                const char* pB = smem + OFF_BHI + (nt * 8 + r) * CH_STRIDE + c * 4 + k0b;
                uint32_t bh0 = *reinterpret_cast<const uint32_t*>(pB);
                uint32_t bh1 = *reinterpret_cast<const uint32_t*>(pB + 16);
                uint32_t bl0 = *reinterpret_cast<const uint32_t*>(pB + (OFF_BLO - OFF_BHI));
                uint32_t bl1 = *reinterpret_cast<const uint32_t*>(pB + (OFF_BLO - OFF_BHI) + 16);
                mma_bf16(acc[nt], ah0, ah1, ah2, ah3, bh0, bh1);
                mma_bf16(acc[nt], ah0, ah1, ah2, ah3, bl0, bl1);
                mma_bf16(acc[nt], al0, al1, al2, al3, bh0, bh1);
            }
        }
        __syncthreads();
    }

    // ---- score epilogue (fp32 accumulators) ----
    {
        float ps0 = 0.f, pt0 = 0.f, ps1 = 0.f, pt1 = 0.f;
        #pragma unroll
        for (int nt = 0; nt < 8; nt++) {
            #pragma unroll
            for (int j = 0; j < 2; j++) {
                int col = nt * 8 + 2 * c + j;
                float av = __ldg(&a[col]);
                float bv = __ldg(&a[64 + col]);
                ps0 = fmaf(acc[nt][j],     av, ps0);
                pt0 = fmaf(acc[nt][j],     bv, pt0);
                ps1 = fmaf(acc[nt][2 + j], av, ps1);
                pt1 = fmaf(acc[nt][2 + j], bv, pt1);
            }
        }
        #pragma unroll
        for (int o = 1; o <= 2; o <<= 1) {
            ps0 += __shfl_xor_sync(0xffffffffu, ps0, o);
            pt0 += __shfl_xor_sync(0xffffffffu, pt0, o);
            ps1 += __shfl_xor_sync(0xffffffffu, ps1, o);
            pt1 += __shfl_xor_sync(0xffffffffu, pt1, o);
        }
        if (c == 0) {
            int n0 = node0 + warp * 16 + r;
            int n1 = n0 + 8;
            if (n0 < n_nodes) { g_ssrc[n0] = ps0; g_strg[n0] = pt0; }
            if (n1 < n_nodes) { g_ssrc[n1] = ps1; g_strg[n1] = pt1; }
        }
    }

    // ---- wx -> half2, restage in smem (stride 36 uints), coalesced STG ----
    unsigned* S = reinterpret_cast<unsigned*>(smem);
    {
        const int row0 = warp * 16 + r;
        #pragma unroll
        for (int nt = 0; nt < 8; nt++) {
            __half2 h0 = __floats2half2_rn(acc[nt][0], acc[nt][1]);
            __half2 h1 = __floats2half2_rn(acc[nt][2], acc[nt][3]);
            S[row0 * 36 + nt * 4 + c]       = *reinterpret_cast<unsigned*>(&h0);
            S[(row0 + 8) * 36 + nt * 4 + c] = *reinterpret_cast<unsigned*>(&h1);
        }
    }
    __syncthreads();
    {
        uint4* wx4 = reinterpret_cast<uint4*>(g_wx16);
        #pragma unroll
        for (int it = 0; it < 4; it++) {
            int idx = tid + it * 256;            // 1024 uint4
            int row = idx >> 3, cq = idx & 7;
            if (node0 + row < n_nodes)
                wx4[(size_t)(node0 + row) * 8 + cq] =
                    *reinterpret_cast<const uint4*>(&S[row * 36 + cq * 4]);
        }
    }
}

// ---------------------------------------------------------------------------
// K2: histogram of src (int4); block 0 zeroes the scan status array.
// ---------------------------------------------------------------------------
__global__ void k_hist(const int* __restrict__ src, int n_edges) {
    if (blockIdx.x == 0 && threadIdx.x < 128) g_stat[threadIdx.x] = 0u;
    int e4 = (blockIdx.x * blockDim.x + threadIdx.x) * 4;
    if (e4 + 3 < n_edges) {
        int4 s = *reinterpret_cast<const int4*>(src + e4);
        atomicAdd(&g_cnt[s.x], 1);
        atomicAdd(&g_cnt[s.y], 1);
        atomicAdd(&g_cnt[s.z], 1);
        atomicAdd(&g_cnt[s.w], 1);
    } else {
        for (int e = e4; e < n_edges; e++) atomicAdd(&g_cnt[src[e]], 1);
    }
}

// ---------------------------------------------------------------------------
// K3: decoupled-lookback exclusive scan; self-clears g_cnt.
// ---------------------------------------------------------------------------
__device__ __forceinline__ int warp_incl_scan(int v, int lane) {
    #pragma unroll
    for (int o = 1; o < 32; o <<= 1) {
        int t = __shfl_up_sync(0xffffffffu, v, o);
        if (lane >= o) v += t;
    }
    return v;
}

__global__ __launch_bounds__(1024) void k_scan_lb(int n, int n_nodes) {
    __shared__ int ws[32];
    __shared__ int s_prev;
    const int tid  = threadIdx.x;
    const int lane = tid & 31;
    const int wid  = tid >> 5;
    const int b    = blockIdx.x;
    const int i    = b * 1024 + tid;

    int v = (i < n) ? g_cnt[i] : 0;
    if (i < n) g_cnt[i] = 0;

    int s = warp_incl_scan(v, lane);
    if (lane == 31) ws[wid] = s;
    __syncthreads();
    if (wid == 0) {
        int bsum = ws[lane];
        int sb = warp_incl_scan(bsum, lane);
        ws[lane] = sb - bsum;
    }
    __syncthreads();
    const int incl = s + ws[wid];

    if (tid == 1023)
        g_stat[b] = (unsigned)incl | (b == 0 ? FLAG_INC : FLAG_AGG);
    __syncthreads();

    if (tid == 0) {
        int prev = 0;
        if (b > 0) {
            int j = b - 1;
            while (true) {
                unsigned st = *(volatile unsigned*)&g_stat[j];
                if (st == 0u) continue;
                prev += (int)(st & VAL_MASK);
                if (st & FLAG_INC) break;
                j--;
            }
        }
        s_prev = prev;
    }
    __syncthreads();
    const int prev = s_prev;

    if (tid == 1023 && b > 0)
        *(volatile unsigned*)&g_stat[b] = ((unsigned)(incl + prev)) | FLAG_INC;

    if (i < n) {
        int excl = prev + incl - v;
        g_rowst[i] = excl;
        if (i < n_nodes) g_curs[i] = excl;
    }
}

// ---------------------------------------------------------------------------
// K4: counting-sort scatter (int4 loads, 4 edges/thread)
// ---------------------------------------------------------------------------
__global__ void k_scatter(const int* __restrict__ src, const int* __restrict__ trg,
                          int n_edges) {
    int e4 = (blockIdx.x * blockDim.x + threadIdx.x) * 4;
    if (e4 + 3 < n_edges) {
        int4 s = *reinterpret_cast<const int4*>(src + e4);
        int4 t = *reinterpret_cast<const int4*>(trg + e4);
        g_perm[atomicAdd(&g_curs[s.x], 1)] = t.x;
        g_perm[atomicAdd(&g_curs[s.y], 1)] = t.y;
        g_perm[atomicAdd(&g_curs[s.z], 1)] = t.z;
        g_perm[atomicAdd(&g_curs[s.w], 1)] = t.w;
    } else {
        for (int e = e4; e < n_edges; e++)
            g_perm[atomicAdd(&g_curs[src[e]], 1)] = trg[e];
    }
}

// ---------------------------------------------------------------------------
// K5: one warp per node; constant-shift exp; fp16 wx gather, fp32 accum.
// ---------------------------------------------------------------------------
__global__ __launch_bounds__(256) void k_aggregate(float* __restrict__ out,
                                                   int n_nodes) {
    const int warp = (blockIdx.x * blockDim.x + threadIdx.x) >> 5;
    const int lane = threadIdx.x & 31;
    if (warp >= n_nodes) return;

    const int beg = g_rowst[warp];
    const int end = g_rowst[warp + 1];
    const int deg = end - beg;
    const float ss = g_ssrc[warp];

    float den = 0.0f;
    float ex_l = 0.0f;
    int   t_l  = 0;

    if (deg <= 32) {
        if (lane < deg) {
            t_l = g_perm[beg + lane];
            float l = ss + g_strg[t_l];
            l = (l >= 0.0f) ? l : 0.2f * l;
            ex_l = __expf(l - SHIFT_C);
            den = ex_l;
        }
    } else {
        for (int i = beg + lane; i < end; i += 32) {
            int t = g_perm[i];
            float l = ss + g_strg[t];
            l = (l >= 0.0f) ? l : 0.2f * l;
            float ex = __expf(l - SHIFT_C);
            g_ex[i] = ex;
            den += ex;
        }
        __syncwarp();
    }
    #pragma unroll
    for (int o = 16; o > 0; o >>= 1)
        den += __shfl_xor_sync(0xffffffffu, den, o);
    const float inv = (den > 0.0f) ? (1.0f / den) : 0.0f;

    float2 acc = make_float2(0.0f, 0.0f);
    if (deg <= 32) {
        for (int j = 0; j < deg; j++) {
            float alpha = __shfl_sync(0xffffffffu, ex_l, j) * inv;
            int   t     = __shfl_sync(0xffffffffu, t_l, j);
            unsigned u = g_wx16[(size_t)t * 32 + lane];
            float2 v = __half22float2(*reinterpret_cast<__half2*>(&u));
            acc.x = fmaf(alpha, v.x, acc.x);
            acc.y = fmaf(alpha, v.y, acc.y);
        }
    } else {
        for (int i = beg; i < end; i++) {
            float alpha = g_ex[i] * inv;
            int   t     = g_perm[i];
            unsigned u = g_wx16[(size_t)t * 32 + lane];
            float2 v = __half22float2(*reinterpret_cast<__half2*>(&u));
            acc.x = fmaf(alpha, v.x, acc.x);
            acc.y = fmaf(alpha, v.y, acc.y);
        }
    }
    *reinterpret_cast<float2*>(&out[(size_t)warp * D_OUT + lane * 2]) = acc;
}

// ---------------------------------------------------------------------------
extern "C" void kernel_launch(void* const* d_in, const int* in_sizes, int n_in,
                              void* d_out, int out_size)
{
    const float* X   = (const float*)d_in[0];
    const float* W   = (const float*)d_in[1];
    const float* a   = (const float*)d_in[2];
    const int*   adj = (const int*)d_in[3];

    const int n_nodes = in_sizes[0] / D_IN;
    const int n_edges = in_sizes[3] / 2;
    const int* src = adj;
    const int* trg = adj + n_edges;
    float* out = (float*)d_out;

    const int nscan = n_nodes + 1;

    static cudaStream_t sB = nullptr;
    static cudaEvent_t  evFork = nullptr, evJoin = nullptr;
    if (sB == nullptr) {
        cudaFuncSetAttribute(k_gemm_mma, cudaFuncAttributeMaxDynamicSharedMemorySize,
                             GEMM_SMEM_BYTES);
        cudaStreamCreateWithFlags(&sB, cudaStreamNonBlocking);
        cudaEventCreateWithFlags(&evFork, cudaEventDisableTiming);
        cudaEventCreateWithFlags(&evJoin, cudaEventDisableTiming);
    }

    // ---- fork ----
    cudaEventRecord(evFork, 0);
    cudaStreamWaitEvent(sB, evFork, 0);

    // chain B: hist -> scan -> scatter
    {
        int e4 = (n_edges + 3) / 4;
        k_hist<<<(e4 + 255) / 256, 256, 0, sB>>>(src, n_edges);
    }
    k_scan_lb<<<(nscan + 1023) / 1024, 1024, 0, sB>>>(nscan, n_nodes);
    {
        int e4 = (n_edges + 3) / 4;
        k_scatter<<<(e4 + 255) / 256, 256, 0, sB>>>(src, trg, n_edges);
    }
    cudaEventRecord(evJoin, sB);

    // chain A
    k_gemm_mma<<<(n_nodes + 127) / 128, 256, GEMM_SMEM_BYTES>>>(X, W, a, n_nodes);

    // ---- join ----
    cudaStreamWaitEvent(0, evJoin, 0);
    {
        long long threads = (long long)n_nodes * 32;
        k_aggregate<<<(int)((threads + 255) / 256), 256>>>(out, n_nodes);
    }
}

// round 9
// speedup vs baseline: 1.0674x; 1.0367x over previous
#include <cuda_runtime.h>
#include <cuda_bf16.h>
#include <cuda_fp16.h>
#include <cstdint>

// GAT layer (sm_100 baseline ISA):
//  Fork/join graph (6 nodes):
//   stream0: K1 GEMM (bf16x3 HMMA, A-from-global, B-ldmatrix) + scores --\
//   streamB: K2 hist -> K3 lookback scan -> K4 scatter                    } -> K5
//  wx stored fp16. Adjacency arrives as int32 (JAX x64 off).

#define D_IN  128
#define D_OUT 64
#define N_NODES_MAX 100000
#define N_EDGES_MAX 1000000
#define NSCAN_PAD   100352
#define SHIFT_C 8.0f

#define FLAG_AGG 0x40000000u
#define FLAG_INC 0x80000000u
#define VAL_MASK 0x3FFFFFFFu

// ---- scratch (__device__ globals; allocation-free rule) ----
__device__ unsigned g_wx16 [N_NODES_MAX * 32];   // half2 pairs, 12.8 MB
__device__ float g_ssrc [N_NODES_MAX];
__device__ float g_strg [N_NODES_MAX];
__device__ int   g_cnt  [NSCAN_PAD];             // zero at load; self-clearing
__device__ int   g_rowst[NSCAN_PAD];
__device__ int   g_curs [NSCAN_PAD];
__device__ unsigned g_stat[128];                 // lookback status; hist zeroes
__device__ int   g_perm [N_EDGES_MAX];
__device__ float g_ex   [N_EDGES_MAX];

// ---- helpers ----
__device__ __forceinline__ uint32_t smem_u32(const void* p) {
    uint32_t a;
    asm("{ .reg .u64 t; cvta.to.shared.u64 t, %1; cvt.u32.u64 %0, t; }"
        : "=r"(a) : "l"(p));
    return a;
}
__device__ __forceinline__ void mma_bf16(float* c, uint32_t a0, uint32_t a1,
                                         uint32_t a2, uint32_t a3,
                                         uint32_t b0, uint32_t b1) {
    asm volatile(
        "mma.sync.aligned.m16n8k16.row.col.f32.bf16.bf16.f32 "
        "{%0,%1,%2,%3}, {%4,%5,%6,%7}, {%8,%9}, {%0,%1,%2,%3};"
        : "+f"(c[0]), "+f"(c[1]), "+f"(c[2]), "+f"(c[3])
        : "r"(a0), "r"(a1), "r"(a2), "r"(a3), "r"(b0), "r"(b1));
}
__device__ __forceinline__ void ldm_x4(uint32_t& r0, uint32_t& r1,
                                       uint32_t& r2, uint32_t& r3, uint32_t addr) {
    asm volatile("ldmatrix.sync.aligned.m8n8.x4.shared.b16 {%0,%1,%2,%3}, [%4];"
                 : "=r"(r0), "=r"(r1), "=r"(r2), "=r"(r3) : "r"(addr));
}
__device__ __forceinline__ uint16_t f2bf_bits(float x) {
    uint16_t u; asm("cvt.rn.bf16.f32 %0, %1;" : "=h"(u) : "f"(x)); return u;
}
__device__ __forceinline__ float bf_bits2f(uint16_t u) {
    return __uint_as_float((uint32_t)u << 16);
}
// split float2 -> packed bf16 hi and residual lo
__device__ __forceinline__ void split2(float2 v, uint32_t& hi, uint32_t& lo) {
    __nv_bfloat162 h = __floats2bfloat162_rn(v.x, v.y);
    float lx = v.x - __low2float(h);
    float ly = v.y - __high2float(h);
    __nv_bfloat162 l = __floats2bfloat162_rn(lx, ly);
    hi = *reinterpret_cast<uint32_t*>(&h);
    lo = *reinterpret_cast<uint32_t*>(&l);
}

// SMEM: B only. [n=64][k=128] bf16, row stride 272B (256 + 16 pad).
#define B_STRIDE 272
#define OFF_BLO  17408
#define GEMM_SMEM_BYTES 34816   // 2 * 64 * 272; staging (18432B) reuses this

// ---------------------------------------------------------------------------
// K1: bf16x3 HMMA GEMM. CTA = 128 rows x 64 cols x K=128, 8 warps.
// A fragments loaded directly from global (no smem staging). B via ldmatrix.
// ---------------------------------------------------------------------------
__global__ __launch_bounds__(256, 2) void k_gemm_mma(
    const float* __restrict__ X, const float* __restrict__ W,
    const float* __restrict__ a, int n_nodes)
{
    extern __shared__ char smem[];
    const uint32_t sB = smem_u32(smem);
    const int tid   = threadIdx.x;
    const int warp  = tid >> 5;
    const int lane  = tid & 31;
    const int r     = lane >> 2;       // 0..7
    const int c     = lane & 3;        // 0..3
    const int node0 = blockIdx.x * 128;

    // ---- load W -> B smem transposed ([n][k]) as bf16 hi/lo ----
    {
        #pragma unroll
        for (int it = 0; it < 32; it++) {
            int idx = tid + it * 256;            // 8192 scalars, coalesced over n
            int k = idx >> 6, n = idx & 63;
            float w = W[idx];                    // W[k][n], idx = k*64+n
            uint16_t h = f2bf_bits(w);
            uint16_t l = f2bf_bits(w - bf_bits2f(h));
            char* pp = smem + n * B_STRIDE + k * 2;
            *reinterpret_cast<uint16_t*>(pp) = h;
            *reinterpret_cast<uint16_t*>(pp + OFF_BLO) = l;
        }
    }

    // ldmatrix lane-constant base addresses (4 x4-instrs cover nt pairs)
    const int tile = lane >> 3;                  // 0..3
    const int rit  = lane & 7;
    uint32_t bbase[4];
    #pragma unroll
    for (int q = 0; q < 4; q++)
        bbase[q] = sB + (uint32_t)(((2 * q + (tile >> 1)) * 8 + rit) * B_STRIDE
                                   + (tile & 1) * 16);

    // A row pointers (fragment rows are warp/thread exclusive)
    const int row0 = node0 + warp * 16 + r;
    const int row1 = row0 + 8;
    const bool v0 = row0 < n_nodes;
    const bool v1 = row1 < n_nodes;
    const float* pX0 = X + (size_t)(v0 ? row0 : 0) * D_IN + c * 2;
    const float* pX1 = X + (size_t)(v1 ? row1 : 0) * D_IN + c * 2;
    const float2 z2 = make_float2(0.f, 0.f);

    __syncthreads();

    float acc[8][4];
    #pragma unroll
    for (int nt = 0; nt < 8; nt++)
        #pragma unroll
        for (int j = 0; j < 4; j++) acc[nt][j] = 0.0f;

    #pragma unroll
    for (int kk = 0; kk < 8; kk++) {
        // ---- A frags from global: rows r/r+8, k = kk*16 + 2c + {0,1,8,9} ----
        float2 x0a = v0 ? *reinterpret_cast<const float2*>(pX0 + kk * 16)     : z2;
        float2 x1a = v1 ? *reinterpret_cast<const float2*>(pX1 + kk * 16)     : z2;
        float2 x0b = v0 ? *reinterpret_cast<const float2*>(pX0 + kk * 16 + 8) : z2;
        float2 x1b = v1 ? *reinterpret_cast<const float2*>(pX1 + kk * 16 + 8) : z2;
        uint32_t ah0, al0, ah1, al1, ah2, al2, ah3, al3;
        split2(x0a, ah0, al0);
        split2(x1a, ah1, al1);
        split2(x0b, ah2, al2);
        split2(x1b, ah3, al3);

        // ---- B frags via ldmatrix, two nt-halves to bound registers ----
        #pragma unroll
        for (int h = 0; h < 2; h++) {
            uint32_t bh0[4], bh1[4], bl0[4], bl1[4];
            #pragma unroll
            for (int qq = 0; qq < 2; qq++) {
                int q = 2 * h + qq;
                uint32_t addr = bbase[q] + kk * 32;
                ldm_x4(bh0[2 * qq], bh1[2 * qq], bh0[2 * qq + 1], bh1[2 * qq + 1], addr);
                ldm_x4(bl0[2 * qq], bl1[2 * qq], bl0[2 * qq + 1], bl1[2 * qq + 1],
                       addr + OFF_BLO);
            }
            #pragma unroll
            for (int j = 0; j < 4; j++) {
                float* A = acc[h * 4 + j];
                mma_bf16(A, ah0, ah1, ah2, ah3, bh0[j], bh1[j]);
                mma_bf16(A, ah0, ah1, ah2, ah3, bl0[j], bl1[j]);
                mma_bf16(A, al0, al1, al2, al3, bh0[j], bh1[j]);
            }
        }
    }

    // ---- score epilogue (fp32 accumulators) ----
    {
        float ps0 = 0.f, pt0 = 0.f, ps1 = 0.f, pt1 = 0.f;
        #pragma unroll
        for (int nt = 0; nt < 8; nt++) {
            #pragma unroll
            for (int j = 0; j < 2; j++) {
                int col = nt * 8 + 2 * c + j;
                float av = __ldg(&a[col]);
                float bv = __ldg(&a[64 + col]);
                ps0 = fmaf(acc[nt][j],     av, ps0);
                pt0 = fmaf(acc[nt][j],     bv, pt0);
                ps1 = fmaf(acc[nt][2 + j], av, ps1);
                pt1 = fmaf(acc[nt][2 + j], bv, pt1);
            }
        }
        #pragma unroll
        for (int o = 1; o <= 2; o <<= 1) {
            ps0 += __shfl_xor_sync(0xffffffffu, ps0, o);
            pt0 += __shfl_xor_sync(0xffffffffu, pt0, o);
            ps1 += __shfl_xor_sync(0xffffffffu, ps1, o);
            pt1 += __shfl_xor_sync(0xffffffffu, pt1, o);
        }
        if (c == 0) {
            if (v0) { g_ssrc[row0] = ps0; g_strg[row0] = pt0; }
            if (v1) { g_ssrc[row1] = ps1; g_strg[row1] = pt1; }
        }
    }

    __syncthreads();   // all warps done reading B; reuse smem for staging

    // ---- wx -> half2, restage in smem (stride 36 uints), coalesced STG ----
    unsigned* S = reinterpret_cast<unsigned*>(smem);
    {
        const int lrow = warp * 16 + r;
        #pragma unroll
        for (int nt = 0; nt < 8; nt++) {
            __half2 h0 = __floats2half2_rn(acc[nt][0], acc[nt][1]);
            __half2 h1 = __floats2half2_rn(acc[nt][2], acc[nt][3]);
            S[lrow * 36 + nt * 4 + c]       = *reinterpret_cast<unsigned*>(&h0);
            S[(lrow + 8) * 36 + nt * 4 + c] = *reinterpret_cast<unsigned*>(&h1);
        }
    }
    __syncthreads();
    {
        uint4* wx4 = reinterpret_cast<uint4*>(g_wx16);
        #pragma unroll
        for (int it = 0; it < 4; it++) {
            int idx = tid + it * 256;            // 1024 uint4
            int row = idx >> 3, cq = idx & 7;
            if (node0 + row < n_nodes)
                wx4[(size_t)(node0 + row) * 8 + cq] =
                    *reinterpret_cast<const uint4*>(&S[row * 36 + cq * 4]);
        }
    }
}

// ---------------------------------------------------------------------------
// K2: histogram of src (int4); block 0 zeroes the scan status array.
// ---------------------------------------------------------------------------
__global__ void k_hist(const int* __restrict__ src, int n_edges) {
    if (blockIdx.x == 0 && threadIdx.x < 128) g_stat[threadIdx.x] = 0u;
    int e4 = (blockIdx.x * blockDim.x + threadIdx.x) * 4;
    if (e4 + 3 < n_edges) {
        int4 s = *reinterpret_cast<const int4*>(src + e4);
        atomicAdd(&g_cnt[s.x], 1);
        atomicAdd(&g_cnt[s.y], 1);
        atomicAdd(&g_cnt[s.z], 1);
        atomicAdd(&g_cnt[s.w], 1);
    } else {
        for (int e = e4; e < n_edges; e++) atomicAdd(&g_cnt[src[e]], 1);
    }
}

// ---------------------------------------------------------------------------
// K3: decoupled-lookback exclusive scan; self-clears g_cnt.
// ---------------------------------------------------------------------------
__device__ __forceinline__ int warp_incl_scan(int v, int lane) {
    #pragma unroll
    for (int o = 1; o < 32; o <<= 1) {
        int t = __shfl_up_sync(0xffffffffu, v, o);
        if (lane >= o) v += t;
    }
    return v;
}

__global__ __launch_bounds__(1024) void k_scan_lb(int n, int n_nodes) {
    __shared__ int ws[32];
    __shared__ int s_prev;
    const int tid  = threadIdx.x;
    const int lane = tid & 31;
    const int wid  = tid >> 5;
    const int b    = blockIdx.x;
    const int i    = b * 1024 + tid;

    int v = (i < n) ? g_cnt[i] : 0;
    if (i < n) g_cnt[i] = 0;

    int s = warp_incl_scan(v, lane);
    if (lane == 31) ws[wid] = s;
    __syncthreads();
    if (wid == 0) {
        int bsum = ws[lane];
        int sb = warp_incl_scan(bsum, lane);
        ws[lane] = sb - bsum;
    }
    __syncthreads();
    const int incl = s + ws[wid];

    if (tid == 1023)
        g_stat[b] = (unsigned)incl | (b == 0 ? FLAG_INC : FLAG_AGG);
    __syncthreads();

    if (tid == 0) {
        int prev = 0;
        if (b > 0) {
            int j = b - 1;
            while (true) {
                unsigned st = *(volatile unsigned*)&g_stat[j];
                if (st == 0u) continue;
                prev += (int)(st & VAL_MASK);
                if (st & FLAG_INC) break;
                j--;
            }
        }
        s_prev = prev;
    }
    __syncthreads();
    const int prev = s_prev;

    if (tid == 1023 && b > 0)
        *(volatile unsigned*)&g_stat[b] = ((unsigned)(incl + prev)) | FLAG_INC;

    if (i < n) {
        int excl = prev + incl - v;
        g_rowst[i] = excl;
        if (i < n_nodes) g_curs[i] = excl;
    }
}

// ---------------------------------------------------------------------------
// K4: counting-sort scatter (int4 loads, 4 edges/thread)
// ---------------------------------------------------------------------------
__global__ void k_scatter(const int* __restrict__ src, const int* __restrict__ trg,
                          int n_edges) {
    int e4 = (blockIdx.x * blockDim.x + threadIdx.x) * 4;
    if (e4 + 3 < n_edges) {
        int4 s = *reinterpret_cast<const int4*>(src + e4);
        int4 t = *reinterpret_cast<const int4*>(trg + e4);
        g_perm[atomicAdd(&g_curs[s.x], 1)] = t.x;
        g_perm[atomicAdd(&g_curs[s.y], 1)] = t.y;
        g_perm[atomicAdd(&g_curs[s.z], 1)] = t.z;
        g_perm[atomicAdd(&g_curs[s.w], 1)] = t.w;
    } else {
        for (int e = e4; e < n_edges; e++)
            g_perm[atomicAdd(&g_curs[src[e]], 1)] = trg[e];
    }
}

// ---------------------------------------------------------------------------
// K5: one warp per node; constant-shift exp; fp16 wx gather, fp32 accum.
// ---------------------------------------------------------------------------
__global__ __launch_bounds__(256) void k_aggregate(float* __restrict__ out,
                                                   int n_nodes) {
    const int warp = (blockIdx.x * blockDim.x + threadIdx.x) >> 5;
    const int lane = threadIdx.x & 31;
    if (warp >= n_nodes) return;

    const int beg = g_rowst[warp];
    const int end = g_rowst[warp + 1];
    const int deg = end - beg;
    const float ss = g_ssrc[warp];

    float den = 0.0f;
    float ex_l = 0.0f;
    int   t_l  = 0;

    if (deg <= 32) {
        if (lane < deg) {
            t_l = g_perm[beg + lane];
            float l = ss + g_strg[t_l];
            l = (l >= 0.0f) ? l : 0.2f * l;
            ex_l = __expf(l - SHIFT_C);
            den = ex_l;
        }
    } else {
        for (int i = beg + lane; i < end; i += 32) {
            int t = g_perm[i];
            float l = ss + g_strg[t];
            l = (l >= 0.0f) ? l : 0.2f * l;
            float ex = __expf(l - SHIFT_C);
            g_ex[i] = ex;
            den += ex;
        }
        __syncwarp();
    }
    #pragma unroll
    for (int o = 16; o > 0; o >>= 1)
        den += __shfl_xor_sync(0xffffffffu, den, o);
    const float inv = (den > 0.0f) ? (1.0f / den) : 0.0f;

    float2 acc = make_float2(0.0f, 0.0f);
    if (deg <= 32) {
        for (int j = 0; j < deg; j++) {
            float alpha = __shfl_sync(0xffffffffu, ex_l, j) * inv;
            int   t     = __shfl_sync(0xffffffffu, t_l, j);
            unsigned u = g_wx16[(size_t)t * 32 + lane];
            float2 v = __half22float2(*reinterpret_cast<__half2*>(&u));
            acc.x = fmaf(alpha, v.x, acc.x);
            acc.y = fmaf(alpha, v.y, acc.y);
        }
    } else {
        for (int i = beg; i < end; i++) {
            float alpha = g_ex[i] * inv;
            int   t     = g_perm[i];
            unsigned u = g_wx16[(size_t)t * 32 + lane];
            float2 v = __half22float2(*reinterpret_cast<__half2*>(&u));
            acc.x = fmaf(alpha, v.x, acc.x);
            acc.y = fmaf(alpha, v.y, acc.y);
        }
    }
    *reinterpret_cast<float2*>(&out[(size_t)warp * D_OUT + lane * 2]) = acc;
}

// ---------------------------------------------------------------------------
extern "C" void kernel_launch(void* const* d_in, const int* in_sizes, int n_in,
                              void* d_out, int out_size)
{
    const float* X   = (const float*)d_in[0];
    const float* W   = (const float*)d_in[1];
    const float* a   = (const float*)d_in[2];
    const int*   adj = (const int*)d_in[3];

    const int n_nodes = in_sizes[0] / D_IN;
    const int n_edges = in_sizes[3] / 2;
    const int* src = adj;
    const int* trg = adj + n_edges;
    float* out = (float*)d_out;

    const int nscan = n_nodes + 1;

    static cudaStream_t sB = nullptr;
    static cudaEvent_t  evFork = nullptr, evJoin = nullptr;
    if (sB == nullptr) {
        cudaFuncSetAttribute(k_gemm_mma, cudaFuncAttributeMaxDynamicSharedMemorySize,
                             GEMM_SMEM_BYTES);
        cudaStreamCreateWithFlags(&sB, cudaStreamNonBlocking);
        cudaEventCreateWithFlags(&evFork, cudaEventDisableTiming);
        cudaEventCreateWithFlags(&evJoin, cudaEventDisableTiming);
    }

    // ---- fork ----
    cudaEventRecord(evFork, 0);
    cudaStreamWaitEvent(sB, evFork, 0);

    // chain B: hist -> scan -> scatter
    {
        int e4 = (n_edges + 3) / 4;
        k_hist<<<(e4 + 255) / 256, 256, 0, sB>>>(src, n_edges);
    }
    k_scan_lb<<<(nscan + 1023) / 1024, 1024, 0, sB>>>(nscan, n_nodes);
    {
        int e4 = (n_edges + 3) / 4;
        k_scatter<<<(e4 + 255) / 256, 256, 0, sB>>>(src, trg, n_edges);
    }
    cudaEventRecord(evJoin, sB);

    // chain A
    k_gemm_mma<<<(n_nodes + 127) / 128, 256, GEMM_SMEM_BYTES>>>(X, W, a, n_nodes);

    // ---- join ----
    cudaStreamWaitEvent(0, evJoin, 0);
    {
        long long threads = (long long)n_nodes * 32;
        k_aggregate<<<(int)((threads + 255) / 256), 256>>>(out, n_nodes);
    }
}

// round 11
// speedup vs baseline: 1.1617x; 1.0883x over previous
#include <cuda_runtime.h>
#include <cuda_bf16.h>
#include <cuda_fp16.h>
#include <cstdint>

// GAT layer (sm_100 baseline ISA):
//  Fork/join graph (6 nodes):
//   stream0: K1 GEMM (bf16x3 HMMA, A-from-global, B-ldmatrix, 3 CTA/SM) --\
//   streamB: K2 hist -> K3 lookback scan -> K4 scatter                     } -> K5
//  wx stored fp16; K5 uses 16 lanes per node with SEGMENT-MASK collectives.
// Adjacency arrives as int32 (JAX x64 off).

#define D_IN  128
#define D_OUT 64
#define N_NODES_MAX 100000
#define N_EDGES_MAX 1000000
#define NSCAN_PAD   100352
#define SHIFT_C 8.0f

#define FLAG_AGG 0x40000000u
#define FLAG_INC 0x80000000u
#define VAL_MASK 0x3FFFFFFFu

// ---- scratch (__device__ globals; allocation-free rule) ----
__device__ unsigned g_wx16 [N_NODES_MAX * 32];   // half2 pairs, 12.8 MB
__device__ float g_ssrc [N_NODES_MAX];
__device__ float g_strg [N_NODES_MAX];
__device__ int   g_cnt  [NSCAN_PAD];             // zero at load; self-clearing
__device__ int   g_rowst[NSCAN_PAD];
__device__ int   g_curs [NSCAN_PAD];
__device__ unsigned g_stat[128];                 // lookback status; hist zeroes
__device__ int   g_perm [N_EDGES_MAX];
__device__ float g_ex   [N_EDGES_MAX];

// ---- helpers ----
__device__ __forceinline__ uint32_t smem_u32(const void* p) {
    uint32_t a;
    asm("{ .reg .u64 t; cvta.to.shared.u64 t, %1; cvt.u32.u64 %0, t; }"
        : "=r"(a) : "l"(p));
    return a;
}
__device__ __forceinline__ void mma_bf16(float* c, uint32_t a0, uint32_t a1,
                                         uint32_t a2, uint32_t a3,
                                         uint32_t b0, uint32_t b1) {
    asm volatile(
        "mma.sync.aligned.m16n8k16.row.col.f32.bf16.bf16.f32 "
        "{%0,%1,%2,%3}, {%4,%5,%6,%7}, {%8,%9}, {%0,%1,%2,%3};"
        : "+f"(c[0]), "+f"(c[1]), "+f"(c[2]), "+f"(c[3])
        : "r"(a0), "r"(a1), "r"(a2), "r"(a3), "r"(b0), "r"(b1));
}
__device__ __forceinline__ void ldm_x4(uint32_t& r0, uint32_t& r1,
                                       uint32_t& r2, uint32_t& r3, uint32_t addr) {
    asm volatile("ldmatrix.sync.aligned.m8n8.x4.shared.b16 {%0,%1,%2,%3}, [%4];"
                 : "=r"(r0), "=r"(r1), "=r"(r2), "=r"(r3) : "r"(addr));
}
__device__ __forceinline__ uint16_t f2bf_bits(float x) {
    uint16_t u; asm("cvt.rn.bf16.f32 %0, %1;" : "=h"(u) : "f"(x)); return u;
}
__device__ __forceinline__ float bf_bits2f(uint16_t u) {
    return __uint_as_float((uint32_t)u << 16);
}
__device__ __forceinline__ void split2(float2 v, uint32_t& hi, uint32_t& lo) {
    __nv_bfloat162 h = __floats2bfloat162_rn(v.x, v.y);
    float lx = v.x - __low2float(h);
    float ly = v.y - __high2float(h);
    __nv_bfloat162 l = __floats2bfloat162_rn(lx, ly);
    hi = *reinterpret_cast<uint32_t*>(&h);
    lo = *reinterpret_cast<uint32_t*>(&l);
}

// SMEM: B only. [n=64][k=128] bf16, row stride 272B (256 + 16 pad).
#define B_STRIDE 272
#define OFF_BLO  17408
#define GEMM_SMEM_BYTES 34816

// ---------------------------------------------------------------------------
// K1: bf16x3 HMMA GEMM. CTA = 128 rows x 64 cols x K=128, 8 warps, 3 CTA/SM.
// ---------------------------------------------------------------------------
__global__ __launch_bounds__(256, 3) void k_gemm_mma(
    const float* __restrict__ X, const float* __restrict__ W,
    const float* __restrict__ a, int n_nodes)
{
    extern __shared__ char smem[];
    const uint32_t sB = smem_u32(smem);
    const int tid   = threadIdx.x;
    const int warp  = tid >> 5;
    const int lane  = tid & 31;
    const int r     = lane >> 2;       // 0..7
    const int c     = lane & 3;        // 0..3
    const int node0 = blockIdx.x * 128;

    // ---- load W -> B smem transposed ([n][k]) as bf16 hi/lo ----
    {
        #pragma unroll
        for (int it = 0; it < 32; it++) {
            int idx = tid + it * 256;
            int k = idx >> 6, n = idx & 63;
            float w = W[idx];
            uint16_t h = f2bf_bits(w);
            uint16_t l = f2bf_bits(w - bf_bits2f(h));
            char* pp = smem + n * B_STRIDE + k * 2;
            *reinterpret_cast<uint16_t*>(pp) = h;
            *reinterpret_cast<uint16_t*>(pp + OFF_BLO) = l;
        }
    }

    const int tile = lane >> 3;
    const int rit  = lane & 7;
    uint32_t bbase[4];
    #pragma unroll
    for (int q = 0; q < 4; q++)
        bbase[q] = sB + (uint32_t)(((2 * q + (tile >> 1)) * 8 + rit) * B_STRIDE
                                   + (tile & 1) * 16);

    const int row0 = node0 + warp * 16 + r;
    const int row1 = row0 + 8;
    const bool v0 = row0 < n_nodes;
    const bool v1 = row1 < n_nodes;
    const float* pX0 = X + (size_t)(v0 ? row0 : 0) * D_IN + c * 2;
    const float* pX1 = X + (size_t)(v1 ? row1 : 0) * D_IN + c * 2;
    const float2 z2 = make_float2(0.f, 0.f);

    __syncthreads();

    float acc[8][4];
    #pragma unroll
    for (int nt = 0; nt < 8; nt++)
        #pragma unroll
        for (int j = 0; j < 4; j++) acc[nt][j] = 0.0f;

    #pragma unroll
    for (int kk = 0; kk < 8; kk++) {
        float2 x0a = v0 ? *reinterpret_cast<const float2*>(pX0 + kk * 16)     : z2;
        float2 x1a = v1 ? *reinterpret_cast<const float2*>(pX1 + kk * 16)     : z2;
        float2 x0b = v0 ? *reinterpret_cast<const float2*>(pX0 + kk * 16 + 8) : z2;
        float2 x1b = v1 ? *reinterpret_cast<const float2*>(pX1 + kk * 16 + 8) : z2;
        uint32_t ah0, al0, ah1, al1, ah2, al2, ah3, al3;
        split2(x0a, ah0, al0);
        split2(x1a, ah1, al1);
        split2(x0b, ah2, al2);
        split2(x1b, ah3, al3);

        #pragma unroll
        for (int h = 0; h < 2; h++) {
            uint32_t bh0[4], bh1[4], bl0[4], bl1[4];
            #pragma unroll
            for (int qq = 0; qq < 2; qq++) {
                int q = 2 * h + qq;
                uint32_t addr = bbase[q] + kk * 32;
                ldm_x4(bh0[2 * qq], bh1[2 * qq], bh0[2 * qq + 1], bh1[2 * qq + 1], addr);
                ldm_x4(bl0[2 * qq], bl1[2 * qq], bl0[2 * qq + 1], bl1[2 * qq + 1],
                       addr + OFF_BLO);
            }
            #pragma unroll
            for (int j = 0; j < 4; j++) {
                float* A = acc[h * 4 + j];
                mma_bf16(A, ah0, ah1, ah2, ah3, bh0[j], bh1[j]);
                mma_bf16(A, ah0, ah1, ah2, ah3, bl0[j], bl1[j]);
                mma_bf16(A, al0, al1, al2, al3, bh0[j], bh1[j]);
            }
        }
    }

    // ---- score epilogue ----
    {
        float ps0 = 0.f, pt0 = 0.f, ps1 = 0.f, pt1 = 0.f;
        #pragma unroll
        for (int nt = 0; nt < 8; nt++) {
            #pragma unroll
            for (int j = 0; j < 2; j++) {
                int col = nt * 8 + 2 * c + j;
                float av = __ldg(&a[col]);
                float bv = __ldg(&a[64 + col]);
                ps0 = fmaf(acc[nt][j],     av, ps0);
                pt0 = fmaf(acc[nt][j],     bv, pt0);
                ps1 = fmaf(acc[nt][2 + j], av, ps1);
                pt1 = fmaf(acc[nt][2 + j], bv, pt1);
            }
        }
        #pragma unroll
        for (int o = 1; o <= 2; o <<= 1) {
            ps0 += __shfl_xor_sync(0xffffffffu, ps0, o);
            pt0 += __shfl_xor_sync(0xffffffffu, pt0, o);
            ps1 += __shfl_xor_sync(0xffffffffu, ps1, o);
            pt1 += __shfl_xor_sync(0xffffffffu, pt1, o);
        }
        if (c == 0) {
            if (v0) { g_ssrc[row0] = ps0; g_strg[row0] = pt0; }
            if (v1) { g_ssrc[row1] = ps1; g_strg[row1] = pt1; }
        }
    }

    __syncthreads();

    // ---- wx -> half2, restage in smem (stride 36 uints), coalesced STG ----
    unsigned* S = reinterpret_cast<unsigned*>(smem);
    {
        const int lrow = warp * 16 + r;
        #pragma unroll
        for (int nt = 0; nt < 8; nt++) {
            __half2 h0 = __floats2half2_rn(acc[nt][0], acc[nt][1]);
            __half2 h1 = __floats2half2_rn(acc[nt][2], acc[nt][3]);
            S[lrow * 36 + nt * 4 + c]       = *reinterpret_cast<unsigned*>(&h0);
            S[(lrow + 8) * 36 + nt * 4 + c] = *reinterpret_cast<unsigned*>(&h1);
        }
    }
    __syncthreads();
    {
        uint4* wx4 = reinterpret_cast<uint4*>(g_wx16);
        #pragma unroll
        for (int it = 0; it < 4; it++) {
            int idx = tid + it * 256;
            int row = idx >> 3, cq = idx & 7;
            if (node0 + row < n_nodes)
                wx4[(size_t)(node0 + row) * 8 + cq] =
                    *reinterpret_cast<const uint4*>(&S[row * 36 + cq * 4]);
        }
    }
}

// ---------------------------------------------------------------------------
// K2: histogram of src (int4); block 0 zeroes the scan status array.
// ---------------------------------------------------------------------------
__global__ void k_hist(const int* __restrict__ src, int n_edges) {
    if (blockIdx.x == 0 && threadIdx.x < 128) g_stat[threadIdx.x] = 0u;
    int e4 = (blockIdx.x * blockDim.x + threadIdx.x) * 4;
    if (e4 + 3 < n_edges) {
        int4 s = *reinterpret_cast<const int4*>(src + e4);
        atomicAdd(&g_cnt[s.x], 1);
        atomicAdd(&g_cnt[s.y], 1);
        atomicAdd(&g_cnt[s.z], 1);
        atomicAdd(&g_cnt[s.w], 1);
    } else {
        for (int e = e4; e < n_edges; e++) atomicAdd(&g_cnt[src[e]], 1);
    }
}

// ---------------------------------------------------------------------------
// K3: decoupled-lookback exclusive scan; self-clears g_cnt.
// ---------------------------------------------------------------------------
__device__ __forceinline__ int warp_incl_scan(int v, int lane) {
    #pragma unroll
    for (int o = 1; o < 32; o <<= 1) {
        int t = __shfl_up_sync(0xffffffffu, v, o);
        if (lane >= o) v += t;
    }
    return v;
}

__global__ __launch_bounds__(1024) void k_scan_lb(int n, int n_nodes) {
    __shared__ int ws[32];
    __shared__ int s_prev;
    const int tid  = threadIdx.x;
    const int lane = tid & 31;
    const int wid  = tid >> 5;
    const int b    = blockIdx.x;
    const int i    = b * 1024 + tid;

    int v = (i < n) ? g_cnt[i] : 0;
    if (i < n) g_cnt[i] = 0;

    int s = warp_incl_scan(v, lane);
    if (lane == 31) ws[wid] = s;
    __syncthreads();
    if (wid == 0) {
        int bsum = ws[lane];
        int sb = warp_incl_scan(bsum, lane);
        ws[lane] = sb - bsum;
    }
    __syncthreads();
    const int incl = s + ws[wid];

    if (tid == 1023)
        g_stat[b] = (unsigned)incl | (b == 0 ? FLAG_INC : FLAG_AGG);
    __syncthreads();

    if (tid == 0) {
        int prev = 0;
        if (b > 0) {
            int j = b - 1;
            while (true) {
                unsigned st = *(volatile unsigned*)&g_stat[j];
                if (st == 0u) continue;
                prev += (int)(st & VAL_MASK);
                if (st & FLAG_INC) break;
                j--;
            }
        }
        s_prev = prev;
    }
    __syncthreads();
    const int prev = s_prev;

    if (tid == 1023 && b > 0)
        *(volatile unsigned*)&g_stat[b] = ((unsigned)(incl + prev)) | FLAG_INC;

    if (i < n) {
        int excl = prev + incl - v;
        g_rowst[i] = excl;
        if (i < n_nodes) g_curs[i] = excl;
    }
}

// ---------------------------------------------------------------------------
// K4: counting-sort scatter (int4 loads, 4 edges/thread)
// ---------------------------------------------------------------------------
__global__ void k_scatter(const int* __restrict__ src, const int* __restrict__ trg,
                          int n_edges) {
    int e4 = (blockIdx.x * blockDim.x + threadIdx.x) * 4;
    if (e4 + 3 < n_edges) {
        int4 s = *reinterpret_cast<const int4*>(src + e4);
        int4 t = *reinterpret_cast<const int4*>(trg + e4);
        g_perm[atomicAdd(&g_curs[s.x], 1)] = t.x;
        g_perm[atomicAdd(&g_curs[s.y], 1)] = t.y;
        g_perm[atomicAdd(&g_curs[s.z], 1)] = t.z;
        g_perm[atomicAdd(&g_curs[s.w], 1)] = t.w;
    } else {
        for (int e = e4; e < n_edges; e++)
            g_perm[atomicAdd(&g_curs[src[e]], 1)] = trg[e];
    }
}

// ---------------------------------------------------------------------------
// K5: 16 lanes per node (2 nodes/warp). ALL collectives use the 16-lane
// segment mask (halves diverge on deg; full-mask ops here deadlock).
// ---------------------------------------------------------------------------
__global__ __launch_bounds__(256) void k_aggregate(float* __restrict__ out,
                                                   int n_nodes) {
    const int gid  = blockIdx.x * blockDim.x + threadIdx.x;
    const int node = gid >> 4;
    const int hl   = threadIdx.x & 15;
    const unsigned m = 0xFFFFu << (threadIdx.x & 0x10);   // segment mask
    if (node >= n_nodes) return;

    const int beg = g_rowst[node];
    const int end = g_rowst[node + 1];
    const int deg = end - beg;
    const float ss = g_ssrc[node];

    float den = 0.0f;
    float ex_l = 0.0f;
    int   t_l  = 0;

    if (deg <= 16) {
        if (hl < deg) {
            t_l = g_perm[beg + hl];
            float l = ss + g_strg[t_l];
            l = (l >= 0.0f) ? l : 0.2f * l;
            ex_l = __expf(l - SHIFT_C);
            den = ex_l;
        }
    } else {
        for (int i = beg + hl; i < end; i += 16) {
            int t = g_perm[i];
            float l = ss + g_strg[t];
            l = (l >= 0.0f) ? l : 0.2f * l;
            float ex = __expf(l - SHIFT_C);
            g_ex[i] = ex;
            den += ex;
        }
        __syncwarp(m);
    }
    #pragma unroll
    for (int o = 8; o > 0; o >>= 1)
        den += __shfl_xor_sync(m, den, o, 16);
    const float inv = (den > 0.0f) ? (1.0f / den) : 0.0f;

    float4 acc = make_float4(0.f, 0.f, 0.f, 0.f);
    if (deg <= 16) {
        for (int j = 0; j < deg; j++) {
            float alpha = __shfl_sync(m, ex_l, j, 16) * inv;
            int   t     = __shfl_sync(m, t_l, j, 16);
            uint2 u = *reinterpret_cast<const uint2*>(&g_wx16[(size_t)t * 32 + hl * 2]);
            float2 v0 = __half22float2(*reinterpret_cast<__half2*>(&u.x));
            float2 v1 = __half22float2(*reinterpret_cast<__half2*>(&u.y));
            acc.x = fmaf(alpha, v0.x, acc.x);
            acc.y = fmaf(alpha, v0.y, acc.y);
            acc.z = fmaf(alpha, v1.x, acc.z);
            acc.w = fmaf(alpha, v1.y, acc.w);
        }
    } else {
        for (int i = beg; i < end; i++) {
            float alpha = g_ex[i] * inv;
            int   t     = g_perm[i];
            uint2 u = *reinterpret_cast<const uint2*>(&g_wx16[(size_t)t * 32 + hl * 2]);
            float2 v0 = __half22float2(*reinterpret_cast<__half2*>(&u.x));
            float2 v1 = __half22float2(*reinterpret_cast<__half2*>(&u.y));
            acc.x = fmaf(alpha, v0.x, acc.x);
            acc.y = fmaf(alpha, v0.y, acc.y);
            acc.z = fmaf(alpha, v1.x, acc.z);
            acc.w = fmaf(alpha, v1.y, acc.w);
        }
    }
    *reinterpret_cast<float4*>(&out[(size_t)node * D_OUT + hl * 4]) = acc;
}

// ---------------------------------------------------------------------------
extern "C" void kernel_launch(void* const* d_in, const int* in_sizes, int n_in,
                              void* d_out, int out_size)
{
    const float* X   = (const float*)d_in[0];
    const float* W   = (const float*)d_in[1];
    const float* a   = (const float*)d_in[2];
    const int*   adj = (const int*)d_in[3];

    const int n_nodes = in_sizes[0] / D_IN;
    const int n_edges = in_sizes[3] / 2;
    const int* src = adj;
    const int* trg = adj + n_edges;
    float* out = (float*)d_out;

    const int nscan = n_nodes + 1;

    static cudaStream_t sB = nullptr;
    static cudaEvent_t  evFork = nullptr, evJoin = nullptr;
    if (sB == nullptr) {
        cudaFuncSetAttribute(k_gemm_mma, cudaFuncAttributeMaxDynamicSharedMemorySize,
                             GEMM_SMEM_BYTES);
        cudaStreamCreateWithFlags(&sB, cudaStreamNonBlocking);
        cudaEventCreateWithFlags(&evFork, cudaEventDisableTiming);
        cudaEventCreateWithFlags(&evJoin, cudaEventDisableTiming);
    }

    // ---- fork ----
    cudaEventRecord(evFork, 0);
    cudaStreamWaitEvent(sB, evFork, 0);

    // chain A issued first (scheduler hint), runs on stream 0
    k_gemm_mma<<<(n_nodes + 127) / 128, 256, GEMM_SMEM_BYTES>>>(X, W, a, n_nodes);

    // chain B: hist -> scan -> scatter on sB
    {
        int e4 = (n_edges + 3) / 4;
        k_hist<<<(e4 + 255) / 256, 256, 0, sB>>>(src, n_edges);
    }
    k_scan_lb<<<(nscan + 1023) / 1024, 1024, 0, sB>>>(nscan, n_nodes);
    {
        int e4 = (n_edges + 3) / 4;
        k_scatter<<<(e4 + 255) / 256, 256, 0, sB>>>(src, trg, n_edges);
    }
    cudaEventRecord(evJoin, sB);

    // ---- join ----
    cudaStreamWaitEvent(0, evJoin, 0);
    {
        long long threads = (long long)n_nodes * 16;
        k_aggregate<<<(int)((threads + 255) / 256), 256>>>(out, n_nodes);
    }
}

// round 12
// speedup vs baseline: 1.1647x; 1.0026x over previous
#include <cuda_runtime.h>
#include <cuda_bf16.h>
#include <cuda_fp16.h>
#include <cstdint>

// GAT layer (sm_100 baseline ISA):
//  Fork/join graph (6 nodes):
//   stream0: K1 GEMM (bf16x3 HMMA, A-from-global, B-ldmatrix, 3 CTA/SM) --\
//   streamB: K2 hist+rank -> K3 lookback scan -> K4 rank-scatter            } -> K5
//  wx stored fp16; K5: 16 lanes/node, segment-mask collectives.
//  Scatter is ATOMIC-FREE: position = rowst[src] + rank (rank from hist).
// Adjacency arrives as int32 (JAX x64 off).

#define D_IN  128
#define D_OUT 64
#define N_NODES_MAX 100000
#define N_EDGES_MAX 1000000
#define NSCAN_PAD   100352
#define SHIFT_C 8.0f

#define FLAG_AGG 0x40000000u
#define FLAG_INC 0x80000000u
#define VAL_MASK 0x3FFFFFFFu

// ---- scratch (__device__ globals; allocation-free rule) ----
__device__ unsigned g_wx16 [N_NODES_MAX * 32];   // half2 pairs, 12.8 MB
__device__ float g_ssrc [N_NODES_MAX];
__device__ float g_strg [N_NODES_MAX];
__device__ int   g_cnt  [NSCAN_PAD];             // zero at load; self-clearing
__device__ int   g_rowst[NSCAN_PAD];
__device__ unsigned g_stat[128];                 // lookback status; hist zeroes
__device__ int   g_rank [N_EDGES_MAX];           // edge rank within its segment
__device__ int   g_perm [N_EDGES_MAX];
__device__ float g_ex   [N_EDGES_MAX];

// ---- helpers ----
__device__ __forceinline__ uint32_t smem_u32(const void* p) {
    uint32_t a;
    asm("{ .reg .u64 t; cvta.to.shared.u64 t, %1; cvt.u32.u64 %0, t; }"
        : "=r"(a) : "l"(p));
    return a;
}
__device__ __forceinline__ void mma_bf16(float* c, uint32_t a0, uint32_t a1,
                                         uint32_t a2, uint32_t a3,
                                         uint32_t b0, uint32_t b1) {
    asm volatile(
        "mma.sync.aligned.m16n8k16.row.col.f32.bf16.bf16.f32 "
        "{%0,%1,%2,%3}, {%4,%5,%6,%7}, {%8,%9}, {%0,%1,%2,%3};"
        : "+f"(c[0]), "+f"(c[1]), "+f"(c[2]), "+f"(c[3])
        : "r"(a0), "r"(a1), "r"(a2), "r"(a3), "r"(b0), "r"(b1));
}
__device__ __forceinline__ void ldm_x4(uint32_t& r0, uint32_t& r1,
                                       uint32_t& r2, uint32_t& r3, uint32_t addr) {
    asm volatile("ldmatrix.sync.aligned.m8n8.x4.shared.b16 {%0,%1,%2,%3}, [%4];"
                 : "=r"(r0), "=r"(r1), "=r"(r2), "=r"(r3) : "r"(addr));
}
__device__ __forceinline__ uint16_t f2bf_bits(float x) {
    uint16_t u; asm("cvt.rn.bf16.f32 %0, %1;" : "=h"(u) : "f"(x)); return u;
}
__device__ __forceinline__ float bf_bits2f(uint16_t u) {
    return __uint_as_float((uint32_t)u << 16);
}
__device__ __forceinline__ void split2(float2 v, uint32_t& hi, uint32_t& lo) {
    __nv_bfloat162 h = __floats2bfloat162_rn(v.x, v.y);
    float lx = v.x - __low2float(h);
    float ly = v.y - __high2float(h);
    __nv_bfloat162 l = __floats2bfloat162_rn(lx, ly);
    hi = *reinterpret_cast<uint32_t*>(&h);
    lo = *reinterpret_cast<uint32_t*>(&l);
}

// SMEM: B only. [n=64][k=128] bf16, row stride 272B (256 + 16 pad).
#define B_STRIDE 272
#define OFF_BLO  17408
#define GEMM_SMEM_BYTES 34816

// ---------------------------------------------------------------------------
// K1: bf16x3 HMMA GEMM. CTA = 128 rows x 64 cols x K=128, 8 warps, 3 CTA/SM.
// ---------------------------------------------------------------------------
__global__ __launch_bounds__(256, 3) void k_gemm_mma(
    const float* __restrict__ X, const float* __restrict__ W,
    const float* __restrict__ a, int n_nodes)
{
    extern __shared__ char smem[];
    const uint32_t sB = smem_u32(smem);
    const int tid   = threadIdx.x;
    const int warp  = tid >> 5;
    const int lane  = tid & 31;
    const int r     = lane >> 2;
    const int c     = lane & 3;
    const int node0 = blockIdx.x * 128;

    // ---- load W -> B smem transposed ([n][k]) as bf16 hi/lo ----
    {
        #pragma unroll
        for (int it = 0; it < 32; it++) {
            int idx = tid + it * 256;
            int k = idx >> 6, n = idx & 63;
            float w = W[idx];
            uint16_t h = f2bf_bits(w);
            uint16_t l = f2bf_bits(w - bf_bits2f(h));
            char* pp = smem + n * B_STRIDE + k * 2;
            *reinterpret_cast<uint16_t*>(pp) = h;
            *reinterpret_cast<uint16_t*>(pp + OFF_BLO) = l;
        }
    }

    const int tile = lane >> 3;
    const int rit  = lane & 7;
    uint32_t bbase[4];
    #pragma unroll
    for (int q = 0; q < 4; q++)
        bbase[q] = sB + (uint32_t)(((2 * q + (tile >> 1)) * 8 + rit) * B_STRIDE
                                   + (tile & 1) * 16);

    const int row0 = node0 + warp * 16 + r;
    const int row1 = row0 + 8;
    const bool v0 = row0 < n_nodes;
    const bool v1 = row1 < n_nodes;
    const float* pX0 = X + (size_t)(v0 ? row0 : 0) * D_IN + c * 2;
    const float* pX1 = X + (size_t)(v1 ? row1 : 0) * D_IN + c * 2;
    const float2 z2 = make_float2(0.f, 0.f);

    __syncthreads();

    float acc[8][4];
    #pragma unroll
    for (int nt = 0; nt < 8; nt++)
        #pragma unroll
        for (int j = 0; j < 4; j++) acc[nt][j] = 0.0f;

    #pragma unroll
    for (int kk = 0; kk < 8; kk++) {
        float2 x0a = v0 ? *reinterpret_cast<const float2*>(pX0 + kk * 16)     : z2;
        float2 x1a = v1 ? *reinterpret_cast<const float2*>(pX1 + kk * 16)     : z2;
        float2 x0b = v0 ? *reinterpret_cast<const float2*>(pX0 + kk * 16 + 8) : z2;
        float2 x1b = v1 ? *reinterpret_cast<const float2*>(pX1 + kk * 16 + 8) : z2;
        uint32_t ah0, al0, ah1, al1, ah2, al2, ah3, al3;
        split2(x0a, ah0, al0);
        split2(x1a, ah1, al1);
        split2(x0b, ah2, al2);
        split2(x1b, ah3, al3);

        #pragma unroll
        for (int h = 0; h < 2; h++) {
            uint32_t bh0[4], bh1[4], bl0[4], bl1[4];
            #pragma unroll
            for (int qq = 0; qq < 2; qq++) {
                int q = 2 * h + qq;
                uint32_t addr = bbase[q] + kk * 32;
                ldm_x4(bh0[2 * qq], bh1[2 * qq], bh0[2 * qq + 1], bh1[2 * qq + 1], addr);
                ldm_x4(bl0[2 * qq], bl1[2 * qq], bl0[2 * qq + 1], bl1[2 * qq + 1],
                       addr + OFF_BLO);
            }
            #pragma unroll
            for (int j = 0; j < 4; j++) {
                float* A = acc[h * 4 + j];
                mma_bf16(A, ah0, ah1, ah2, ah3, bh0[j], bh1[j]);
                mma_bf16(A, ah0, ah1, ah2, ah3, bl0[j], bl1[j]);
                mma_bf16(A, al0, al1, al2, al3, bh0[j], bh1[j]);
            }
        }
    }

    // ---- score epilogue ----
    {
        float ps0 = 0.f, pt0 = 0.f, ps1 = 0.f, pt1 = 0.f;
        #pragma unroll
        for (int nt = 0; nt < 8; nt++) {
            #pragma unroll
            for (int j = 0; j < 2; j++) {
                int col = nt * 8 + 2 * c + j;
                float av = __ldg(&a[col]);
                float bv = __ldg(&a[64 + col]);
                ps0 = fmaf(acc[nt][j],     av, ps0);
                pt0 = fmaf(acc[nt][j],     bv, pt0);
                ps1 = fmaf(acc[nt][2 + j], av, ps1);
                pt1 = fmaf(acc[nt][2 + j], bv, pt1);
            }
        }
        #pragma unroll
        for (int o = 1; o <= 2; o <<= 1) {
            ps0 += __shfl_xor_sync(0xffffffffu, ps0, o);
            pt0 += __shfl_xor_sync(0xffffffffu, pt0, o);
            ps1 += __shfl_xor_sync(0xffffffffu, ps1, o);
            pt1 += __shfl_xor_sync(0xffffffffu, pt1, o);
        }
        if (c == 0) {
            if (v0) { g_ssrc[row0] = ps0; g_strg[row0] = pt0; }
            if (v1) { g_ssrc[row1] = ps1; g_strg[row1] = pt1; }
        }
    }

    __syncthreads();

    // ---- wx -> half2, restage in smem (stride 36 uints), coalesced STG ----
    unsigned* S = reinterpret_cast<unsigned*>(smem);
    {
        const int lrow = warp * 16 + r;
        #pragma unroll
        for (int nt = 0; nt < 8; nt++) {
            __half2 h0 = __floats2half2_rn(acc[nt][0], acc[nt][1]);
            __half2 h1 = __floats2half2_rn(acc[nt][2], acc[nt][3]);
            S[lrow * 36 + nt * 4 + c]       = *reinterpret_cast<unsigned*>(&h0);
            S[(lrow + 8) * 36 + nt * 4 + c] = *reinterpret_cast<unsigned*>(&h1);
        }
    }
    __syncthreads();
    {
        uint4* wx4 = reinterpret_cast<uint4*>(g_wx16);
        #pragma unroll
        for (int it = 0; it < 4; it++) {
            int idx = tid + it * 256;
            int row = idx >> 3, cq = idx & 7;
            if (node0 + row < n_nodes)
                wx4[(size_t)(node0 + row) * 8 + cq] =
                    *reinterpret_cast<const uint4*>(&S[row * 36 + cq * 4]);
        }
    }
}

// ---------------------------------------------------------------------------
// K2: histogram + rank. rank[e] = fetch-add on cnt[src[e]].
// Block 0 zeroes the scan status array.
// ---------------------------------------------------------------------------
__global__ void k_hist(const int* __restrict__ src, int n_edges) {
    if (blockIdx.x == 0 && threadIdx.x < 128) g_stat[threadIdx.x] = 0u;
    int e4 = (blockIdx.x * blockDim.x + threadIdx.x) * 4;
    if (e4 + 3 < n_edges) {
        int4 s = *reinterpret_cast<const int4*>(src + e4);
        int4 rk;
        rk.x = atomicAdd(&g_cnt[s.x], 1);
        rk.y = atomicAdd(&g_cnt[s.y], 1);
        rk.z = atomicAdd(&g_cnt[s.z], 1);
        rk.w = atomicAdd(&g_cnt[s.w], 1);
        *reinterpret_cast<int4*>(g_rank + e4) = rk;
    } else {
        for (int e = e4; e < n_edges; e++)
            g_rank[e] = atomicAdd(&g_cnt[src[e]], 1);
    }
}

// ---------------------------------------------------------------------------
// K3: decoupled-lookback exclusive scan; self-clears g_cnt.
// ---------------------------------------------------------------------------
__device__ __forceinline__ int warp_incl_scan(int v, int lane) {
    #pragma unroll
    for (int o = 1; o < 32; o <<= 1) {
        int t = __shfl_up_sync(0xffffffffu, v, o);
        if (lane >= o) v += t;
    }
    return v;
}

__global__ __launch_bounds__(1024) void k_scan_lb(int n) {
    __shared__ int ws[32];
    __shared__ int s_prev;
    const int tid  = threadIdx.x;
    const int lane = tid & 31;
    const int wid  = tid >> 5;
    const int b    = blockIdx.x;
    const int i    = b * 1024 + tid;

    int v = (i < n) ? g_cnt[i] : 0;
    if (i < n) g_cnt[i] = 0;

    int s = warp_incl_scan(v, lane);
    if (lane == 31) ws[wid] = s;
    __syncthreads();
    if (wid == 0) {
        int bsum = ws[lane];
        int sb = warp_incl_scan(bsum, lane);
        ws[lane] = sb - bsum;
    }
    __syncthreads();
    const int incl = s + ws[wid];

    if (tid == 1023)
        g_stat[b] = (unsigned)incl | (b == 0 ? FLAG_INC : FLAG_AGG);
    __syncthreads();

    if (tid == 0) {
        int prev = 0;
        if (b > 0) {
            int j = b - 1;
            while (true) {
                unsigned st = *(volatile unsigned*)&g_stat[j];
                if (st == 0u) continue;
                prev += (int)(st & VAL_MASK);
                if (st & FLAG_INC) break;
                j--;
            }
        }
        s_prev = prev;
    }
    __syncthreads();
    const int prev = s_prev;

    if (tid == 1023 && b > 0)
        *(volatile unsigned*)&g_stat[b] = ((unsigned)(incl + prev)) | FLAG_INC;

    if (i < n) g_rowst[i] = prev + incl - v;
}

// ---------------------------------------------------------------------------
// K4: atomic-free scatter: perm[rowst[src] + rank] = trg
// ---------------------------------------------------------------------------
__global__ void k_scatter(const int* __restrict__ src, const int* __restrict__ trg,
                          int n_edges) {
    int e4 = (blockIdx.x * blockDim.x + threadIdx.x) * 4;
    if (e4 + 3 < n_edges) {
        int4 s  = *reinterpret_cast<const int4*>(src + e4);
        int4 rk = *reinterpret_cast<const int4*>(g_rank + e4);
        int4 t  = *reinterpret_cast<const int4*>(trg + e4);
        g_perm[g_rowst[s.x] + rk.x] = t.x;
        g_perm[g_rowst[s.y] + rk.y] = t.y;
        g_perm[g_rowst[s.z] + rk.z] = t.z;
        g_perm[g_rowst[s.w] + rk.w] = t.w;
    } else {
        for (int e = e4; e < n_edges; e++)
            g_perm[g_rowst[src[e]] + g_rank[e]] = trg[e];
    }
}

// ---------------------------------------------------------------------------
// K5: 16 lanes per node (2 nodes/warp), segment-mask collectives.
// ---------------------------------------------------------------------------
__global__ __launch_bounds__(256) void k_aggregate(float* __restrict__ out,
                                                   int n_nodes) {
    const int gid  = blockIdx.x * blockDim.x + threadIdx.x;
    const int node = gid >> 4;
    const int hl   = threadIdx.x & 15;
    const unsigned m = 0xFFFFu << (threadIdx.x & 0x10);
    if (node >= n_nodes) return;

    const int beg = g_rowst[node];
    const int end = g_rowst[node + 1];
    const int deg = end - beg;
    const float ss = g_ssrc[node];

    float den = 0.0f;
    float ex_l = 0.0f;
    int   t_l  = 0;

    if (deg <= 16) {
        if (hl < deg) {
            t_l = g_perm[beg + hl];
            float l = ss + g_strg[t_l];
            l = (l >= 0.0f) ? l : 0.2f * l;
            ex_l = __expf(l - SHIFT_C);
            den = ex_l;
        }
    } else {
        for (int i = beg + hl; i < end; i += 16) {
            int t = g_perm[i];
            float l = ss + g_strg[t];
            l = (l >= 0.0f) ? l : 0.2f * l;
            float ex = __expf(l - SHIFT_C);
            g_ex[i] = ex;
            den += ex;
        }
        __syncwarp(m);
    }
    #pragma unroll
    for (int o = 8; o > 0; o >>= 1)
        den += __shfl_xor_sync(m, den, o, 16);
    const float inv = (den > 0.0f) ? (1.0f / den) : 0.0f;

    float4 acc = make_float4(0.f, 0.f, 0.f, 0.f);
    if (deg <= 16) {
        for (int j = 0; j < deg; j++) {
            float alpha = __shfl_sync(m, ex_l, j, 16) * inv;
            int   t     = __shfl_sync(m, t_l, j, 16);
            uint2 u = *reinterpret_cast<const uint2*>(&g_wx16[(size_t)t * 32 + hl * 2]);
            float2 v0 = __half22float2(*reinterpret_cast<__half2*>(&u.x));
            float2 v1 = __half22float2(*reinterpret_cast<__half2*>(&u.y));
            acc.x = fmaf(alpha, v0.x, acc.x);
            acc.y = fmaf(alpha, v0.y, acc.y);
            acc.z = fmaf(alpha, v1.x, acc.z);
            acc.w = fmaf(alpha, v1.y, acc.w);
        }
    } else {
        for (int i = beg; i < end; i++) {
            float alpha = g_ex[i] * inv;
            int   t     = g_perm[i];
            uint2 u = *reinterpret_cast<const uint2*>(&g_wx16[(size_t)t * 32 + hl * 2]);
            float2 v0 = __half22float2(*reinterpret_cast<__half2*>(&u.x));
            float2 v1 = __half22float2(*reinterpret_cast<__half2*>(&u.y));
            acc.x = fmaf(alpha, v0.x, acc.x);
            acc.y = fmaf(alpha, v0.y, acc.y);
            acc.z = fmaf(alpha, v1.x, acc.z);
            acc.w = fmaf(alpha, v1.y, acc.w);
        }
    }
    *reinterpret_cast<float4*>(&out[(size_t)node * D_OUT + hl * 4]) = acc;
}

// ---------------------------------------------------------------------------
extern "C" void kernel_launch(void* const* d_in, const int* in_sizes, int n_in,
                              void* d_out, int out_size)
{
    const float* X   = (const float*)d_in[0];
    const float* W   = (const float*)d_in[1];
    const float* a   = (const float*)d_in[2];
    const int*   adj = (const int*)d_in[3];

    const int n_nodes = in_sizes[0] / D_IN;
    const int n_edges = in_sizes[3] / 2;
    const int* src = adj;
    const int* trg = adj + n_edges;
    float* out = (float*)d_out;

    const int nscan = n_nodes + 1;

    static cudaStream_t sB = nullptr;
    static cudaEvent_t  evFork = nullptr, evJoin = nullptr;
    if (sB == nullptr) {
        cudaFuncSetAttribute(k_gemm_mma, cudaFuncAttributeMaxDynamicSharedMemorySize,
                             GEMM_SMEM_BYTES);
        cudaStreamCreateWithFlags(&sB, cudaStreamNonBlocking);
        cudaEventCreateWithFlags(&evFork, cudaEventDisableTiming);
        cudaEventCreateWithFlags(&evJoin, cudaEventDisableTiming);
    }

    // ---- fork ----
    cudaEventRecord(evFork, 0);
    cudaStreamWaitEvent(sB, evFork, 0);

    // chain A issued first, runs on stream 0
    k_gemm_mma<<<(n_nodes + 127) / 128, 256, GEMM_SMEM_BYTES>>>(X, W, a, n_nodes);

    // chain B: hist+rank -> scan -> atomic-free scatter on sB
    {
        int e4 = (n_edges + 3) / 4;
        k_hist<<<(e4 + 255) / 256, 256, 0, sB>>>(src, n_edges);
    }
    k_scan_lb<<<(nscan + 1023) / 1024, 1024, 0, sB>>>(nscan);
    {
        int e4 = (n_edges + 3) / 4;
        k_scatter<<<(e4 + 255) / 256, 256, 0, sB>>>(src, trg, n_edges);
    }
    cudaEventRecord(evJoin, sB);

    // ---- join ----
    cudaStreamWaitEvent(0, evJoin, 0);
    {
        long long threads = (long long)n_nodes * 16;
        k_aggregate<<<(int)((threads + 255) / 256), 256>>>(out, n_nodes);
    }
}